// round 3
// baseline (speedup 1.0000x reference)
#include <cuda_runtime.h>
#include <cuda_bf16.h>
#include <math.h>

// ---------------- problem constants ----------------
#define B_    64
#define C_    256
#define NPIX  2304          // 48*48
#define BN_TOT (B_ * NPIX)  // 147456 pixels
#define NH_   8
#define DH_   32
#define M_    64
#define DFF_  512

// ---------------- scratch (no allocs allowed -> __device__ globals) ----------------
__device__ float g_kp[C_ * M_];                       // K proj [chan][m], batch-invariant
__device__ float g_vp[C_ * M_];                       // V proj [chan][m]
__device__ float g_Q [(size_t)B_ * C_  * NPIX];       // Q proj, later reused for "merged"
__device__ float g_X [(size_t)B_ * C_  * NPIX];       // attention out, later reused for "src"
__device__ float g_O [(size_t)B_ * C_  * NPIX];       // cos-reweighted "out"
__device__ float g_H1[(size_t)B_ * DFF_ * NPIX];      // FFN hidden

// ---------------- fast exp on the FMA pipe (avoids MUFU bottleneck) ----------------
// exp(x) = 2^(x*log2e); degree-6 poly for 2^f on [0,1). rel err ~1.5e-5.
__device__ __forceinline__ float fast_exp(float x) {
    x = fmaxf(x, -80.0f);
    float y  = x * 1.4426950408889634f;
    float fk = floorf(y);
    float f  = y - fk;
    float p  = 1.5398e-4f;                 // ln2^6/720
    p = fmaf(p, f, 1.3333558e-3f);         // ln2^5/120
    p = fmaf(p, f, 9.6181291e-3f);         // ln2^4/24
    p = fmaf(p, f, 5.5504109e-2f);         // ln2^3/6
    p = fmaf(p, f, 2.4022651e-1f);         // ln2^2/2
    p = fmaf(p, f, 6.9314718e-1f);         // ln2
    p = fmaf(p, f, 1.0f);
    return __int_as_float(((int)fk + 127) << 23) * p;
}

// ---------------- K0: K/V projections (batch-invariant, tiny) ----------------
// kp[o][m] = sum_c wk[o][c]*bcw[m][c] + bk[o]  (same for v)
__global__ void kv_proj(const float* __restrict__ wk, const float* __restrict__ bk,
                        const float* __restrict__ wv, const float* __restrict__ bv,
                        const float* __restrict__ bcw)
{
    __shared__ float bs[C_];
    int m = blockIdx.x;      // 0..63
    int o = threadIdx.x;     // 0..255
    bs[o] = bcw[m * C_ + o];
    __syncthreads();
    float ak = bk[o], av = bv[o];
    const float* wkr = wk + (size_t)o * C_;
    const float* wvr = wv + (size_t)o * C_;
#pragma unroll 8
    for (int c = 0; c < C_; c++) {
        ak = fmaf(wkr[c], bs[c], ak);
        av = fmaf(wvr[c], bs[c], av);
    }
    g_kp[o * M_ + m] = ak;
    g_vp[o * M_ + m] = av;
}

// ---------------- generic tiled SGEMM: Y = act(W @ X + bias [+ resid]) ----------------
// W: [R][K] row-major.  X, Y, resid: [B][K or R][NPIX] (columns = pixels, contiguous n).
// Tile 128x128, BK=32, 256 threads, 8x8 microtile. 32 KB static smem.
#define BM  128
#define BNT 128
#define BK  32

__global__ __launch_bounds__(256, 2)
void gemm_bias_act(const float* __restrict__ W, const float* __restrict__ X,
                   const float* __restrict__ bias, const float* __restrict__ resid,
                   float* __restrict__ Y, int R, int K, int act)
{
    __shared__ float Ws[BK][BM];
    __shared__ float Xs[BK][BNT];

    const int tid = threadIdx.x;
    const int j0  = blockIdx.x * BNT;      // global pixel tile (2304 % 128 == 0 -> never crosses batch)
    const int b   = j0 / NPIX;
    const int n0  = j0 - b * NPIX;
    const int m0  = blockIdx.y * BM;

    const float* Xb = X + (size_t)b * K * NPIX + n0;

    const int tm = tid >> 4;               // 0..15
    const int tj = tid & 15;               // 0..15

    float acc[8][8];
#pragma unroll
    for (int i = 0; i < 8; i++)
#pragma unroll
        for (int j = 0; j < 8; j++) acc[i][j] = 0.0f;

    const int wk_ = tid & 31;              // k within tile for W loads (coalesced over K)
    const int wm_ = tid >> 5;              // base row
    const int xj_ = tid & 127;             // pixel for X loads (coalesced over n)
    const int xk_ = tid >> 7;

    for (int k0 = 0; k0 < K; k0 += BK) {
#pragma unroll
        for (int p = 0; p < 16; p++) {
            int m = wm_ + p * 8;
            Ws[wk_][m] = W[(size_t)(m0 + m) * K + k0 + wk_];
        }
#pragma unroll
        for (int p = 0; p < 16; p++) {
            int k = xk_ + p * 2;
            Xs[k][xj_] = Xb[(size_t)(k0 + k) * NPIX + xj_];
        }
        __syncthreads();

#pragma unroll 8
        for (int k = 0; k < BK; k++) {
            float4 w0 = *(const float4*)&Ws[k][tm * 8];
            float4 w1 = *(const float4*)&Ws[k][tm * 8 + 4];
            float4 x0 = *(const float4*)&Xs[k][tj * 8];
            float4 x1 = *(const float4*)&Xs[k][tj * 8 + 4];
            float wf[8] = {w0.x, w0.y, w0.z, w0.w, w1.x, w1.y, w1.z, w1.w};
            float xf[8] = {x0.x, x0.y, x0.z, x0.w, x1.x, x1.y, x1.z, x1.w};
#pragma unroll
            for (int i = 0; i < 8; i++)
#pragma unroll
                for (int j = 0; j < 8; j++)
                    acc[i][j] = fmaf(wf[i], xf[j], acc[i][j]);
        }
        __syncthreads();
    }

    const int colg = n0 + tj * 8;
#pragma unroll
    for (int i = 0; i < 8; i++) {
        int row = m0 + tm * 8 + i;
        float bi = bias[row];
        size_t off = ((size_t)b * R + row) * NPIX + colg;
#pragma unroll
        for (int j = 0; j < 8; j++) {
            float v = acc[i][j] + bi;
            if (resid) v += resid[off + j];
            if (act)   v = fmaxf(v, 0.0f);
            Y[off + j] = v;
        }
    }
}

// ---------------- attention: per-thread pixel, per-block head ----------------
// scores[m] = (q_d . kp[d][h][m]) / sqrt(32); softmax over m; x[d] = sum_m p[m]*vp[d][h][m]
__global__ __launch_bounds__(128)
void attn_kernel(const float* __restrict__ Q, float* __restrict__ Xout)
{
    __shared__ float kps[DH_][M_];
    __shared__ float vps[DH_][M_];
    const int h   = blockIdx.y;
    const int tid = threadIdx.x;

    for (int i = tid; i < DH_ * M_; i += 128) {
        int d = i >> 6, m = i & 63;
        kps[d][m] = g_kp[(d * NH_ + h) * M_ + m];
        vps[d][m] = g_vp[(d * NH_ + h) * M_ + m];
    }
    __syncthreads();

    const int j = blockIdx.x * 128 + tid;
    const int b = j / NPIX;
    const int n = j - b * NPIX;
    const float* Qb = Q + (size_t)b * C_ * NPIX + n;

    float s[M_];
#pragma unroll
    for (int m = 0; m < M_; m++) s[m] = 0.0f;
#pragma unroll
    for (int d = 0; d < DH_; d++) {
        float qd = Qb[(size_t)(d * NH_ + h) * NPIX];
#pragma unroll
        for (int m = 0; m < M_; m++) s[m] = fmaf(qd, kps[d][m], s[m]);
    }

    float mx = s[0];
#pragma unroll
    for (int m = 1; m < M_; m++) mx = fmaxf(mx, s[m]);
    float ssum = 0.0f;
#pragma unroll
    for (int m = 0; m < M_; m++) {
        float e = fast_exp((s[m] - mx) * 0.17677669529663687f);  // 1/sqrt(32)
        s[m] = e;
        ssum += e;
    }
    float inv = 1.0f / ssum;

    float* Xb = Xout + (size_t)b * C_ * NPIX + n;
#pragma unroll
    for (int d = 0; d < DH_; d++) {
        float acc = 0.0f;
#pragma unroll
        for (int m = 0; m < M_; m++) acc = fmaf(s[m], vps[d][m], acc);
        Xb[(size_t)(d * NH_ + h) * NPIX] = acc * inv;
    }
}

// ---------------- cosine reweighting: out = feat * (cos(merged, feat) + 1) ----------------
__global__ void cos_kernel(const float* __restrict__ merged, const float* __restrict__ feat,
                           float* __restrict__ out)
{
    const int j = blockIdx.x * 256 + threadIdx.x;
    const int b = j / NPIX;
    const int n = j - b * NPIX;
    const size_t base = (size_t)b * C_ * NPIX + n;
    const float* mc = merged + base;
    const float* fc = feat + base;
    float dot = 0.0f, nm = 0.0f, nf = 0.0f;
#pragma unroll 8
    for (int c = 0; c < C_; c++) {
        float a = mc[(size_t)c * NPIX];
        float f = fc[(size_t)c * NPIX];
        dot = fmaf(a, f, dot);
        nm  = fmaf(a, a, nm);
        nf  = fmaf(f, f, nf);
    }
    float sc = dot / ((sqrtf(nm) + 1e-5f) * (sqrtf(nf) + 1e-5f)) + 1.0f;
    float* oc = out + base;
#pragma unroll 8
    for (int c = 0; c < C_; c++)
        oc[(size_t)c * NPIX] = fc[(size_t)c * NPIX] * sc;
}

// ---------------- LayerNorm over channels, writes final [B][C][N] output ----------------
__global__ void ln_kernel(const float* __restrict__ src, const float* __restrict__ gamma,
                          const float* __restrict__ beta, float* __restrict__ out)
{
    const int j = blockIdx.x * 256 + threadIdx.x;
    const int b = j / NPIX;
    const int n = j - b * NPIX;
    const size_t base = (size_t)b * C_ * NPIX + n;
    const float* sc = src + base;
    float s = 0.0f, s2 = 0.0f;
#pragma unroll 8
    for (int c = 0; c < C_; c++) {
        float v = sc[(size_t)c * NPIX];
        s += v;
        s2 = fmaf(v, v, s2);
    }
    float mu  = s * (1.0f / C_);
    float var = s2 * (1.0f / C_) - mu * mu;
    float inv = rsqrtf(var + 1e-5f);
    float* oc = out + base;
#pragma unroll 8
    for (int c = 0; c < C_; c++)
        oc[(size_t)c * NPIX] = (sc[(size_t)c * NPIX] - mu) * inv * gamma[c] + beta[c];
}

// ---------------- host orchestration ----------------
extern "C" void kernel_launch(void* const* d_in, const int* in_sizes, int n_in,
                              void* d_out, int out_size)
{
    const float* feature = (const float*)d_in[0];
    const float* bcw     = (const float*)d_in[1];
    const float* wq      = (const float*)d_in[2];
    const float* bq      = (const float*)d_in[3];
    const float* wk      = (const float*)d_in[4];
    const float* bk      = (const float*)d_in[5];
    const float* wv      = (const float*)d_in[6];
    const float* bv      = (const float*)d_in[7];
    const float* wm      = (const float*)d_in[8];
    const float* bm      = (const float*)d_in[9];
    const float* w1      = (const float*)d_in[10];
    const float* b1      = (const float*)d_in[11];
    const float* w2      = (const float*)d_in[12];
    const float* b2      = (const float*)d_in[13];
    const float* gamma   = (const float*)d_in[14];
    const float* beta    = (const float*)d_in[15];
    float* out = (float*)d_out;

    float *pQ, *pX, *pO, *pH1;
    cudaGetSymbolAddress((void**)&pQ,  g_Q);
    cudaGetSymbolAddress((void**)&pX,  g_X);
    cudaGetSymbolAddress((void**)&pO,  g_O);
    cudaGetSymbolAddress((void**)&pH1, g_H1);

    // 1. K/V projections (batch-invariant, tiny)
    kv_proj<<<M_, C_>>>(wk, bk, wv, bv, bcw);

    // 2. Q = wq @ feat + bq          -> g_Q
    dim3 gC(BN_TOT / BNT, C_ / BM);          // (1152, 2)
    gemm_bias_act<<<gC, 256>>>(wq, feature, bq, nullptr, pQ, C_, C_, 0);

    // 3. attention                    -> g_X
    attn_kernel<<<dim3(BN_TOT / 128, NH_), 128>>>(pQ, pX);

    // 4. merged = wm @ X + bm         -> g_Q (Q is dead)
    gemm_bias_act<<<gC, 256>>>(wm, pX, bm, nullptr, pQ, C_, C_, 0);

    // 5. cosine reweight               -> g_O
    cos_kernel<<<BN_TOT / 256, 256>>>(pQ, feature, pO);

    // 6. H1 = relu(w1 @ out + b1)      -> g_H1
    dim3 gF(BN_TOT / BNT, DFF_ / BM);        // (1152, 4)
    gemm_bias_act<<<gF, 256>>>(w1, pO, b1, nullptr, pH1, DFF_, C_, 1);

    // 7. src = out + w2 @ H1 + b2      -> g_X (attn out is dead)
    gemm_bias_act<<<gC, 256>>>(w2, pH1, b2, pO, pX, C_, DFF_, 0);

    // 8. LayerNorm -> final output [B][C][H][W]
    ln_kernel<<<BN_TOT / 256, 256>>>(pX, gamma, beta, out);
}

// round 8
// speedup vs baseline: 2.7981x; 2.7981x over previous
#include <cuda_runtime.h>
#include <cuda_bf16.h>
#include <math.h>
#include <stdint.h>

// ---------------- problem constants ----------------
#define B_    64
#define C_    256
#define NPIX  2304          // 48*48
#define BN_TOT (B_ * NPIX)  // 147456 pixels
#define NH_   8
#define DH_   32
#define M_    64
#define DFF_  512

// ---------------- scratch (__device__ globals; no allocs allowed) ----------------
__device__ float g_kp[C_ * M_];
__device__ float g_vp[C_ * M_];
__device__ float g_Q [(size_t)B_ * C_  * NPIX];
__device__ float g_X [(size_t)B_ * C_  * NPIX];
__device__ float g_O [(size_t)B_ * C_  * NPIX];
__device__ float g_H1[(size_t)B_ * DFF_ * NPIX];
// pre-split + pre-tiled weight blocks: per (rowtile rt, kchunk kc):
//   10240 bf16 = [hi: 128 rows x 40][lo: 128 x 40], rows padded to 40 (80B, 16B-aligned)
__device__ __align__(16) __nv_bfloat16 g_wqb[(size_t)2  * 8  * 10240];
__device__ __align__(16) __nv_bfloat16 g_wmb[(size_t)2  * 8  * 10240];
__device__ __align__(16) __nv_bfloat16 g_w1b[(size_t)4  * 8  * 10240];
__device__ __align__(16) __nv_bfloat16 g_w2b[(size_t)2  * 16 * 10240];

// ---------------- fast exp on the FMA pipe ----------------
__device__ __forceinline__ float fast_exp(float x) {
    x = fmaxf(x, -80.0f);
    float y  = x * 1.4426950408889634f;
    float fk = floorf(y);
    float f  = y - fk;
    float p  = 1.5398e-4f;
    p = fmaf(p, f, 1.3333558e-3f);
    p = fmaf(p, f, 9.6181291e-3f);
    p = fmaf(p, f, 5.5504109e-2f);
    p = fmaf(p, f, 2.4022651e-1f);
    p = fmaf(p, f, 6.9314718e-1f);
    p = fmaf(p, f, 1.0f);
    return __int_as_float(((int)fk + 127) << 23) * p;
}

// ---------------- mma / ldmatrix helpers ----------------
__device__ __forceinline__ void mma_bf16(float* d, const uint32_t* a, const uint32_t* b) {
    asm volatile("mma.sync.aligned.m16n8k16.row.col.f32.bf16.bf16.f32 "
        "{%0,%1,%2,%3}, {%4,%5,%6,%7}, {%8,%9}, {%0,%1,%2,%3};"
        : "+f"(d[0]), "+f"(d[1]), "+f"(d[2]), "+f"(d[3])
        : "r"(a[0]), "r"(a[1]), "r"(a[2]), "r"(a[3]), "r"(b[0]), "r"(b[1]));
}
__device__ __forceinline__ void ldsm4(uint32_t* r, uint32_t addr) {
    asm volatile("ldmatrix.sync.aligned.m8n8.x4.shared.b16 {%0,%1,%2,%3}, [%4];"
        : "=r"(r[0]), "=r"(r[1]), "=r"(r[2]), "=r"(r[3]) : "r"(addr));
}
__device__ __forceinline__ void ldsm2(uint32_t* r, uint32_t addr) {
    asm volatile("ldmatrix.sync.aligned.m8n8.x2.shared.b16 {%0,%1}, [%2];"
        : "=r"(r[0]), "=r"(r[1]) : "r"(addr));
}

// ---------------- weight split/tiling prep (tiny, rerun every call) ----------------
__global__ void wsplit(const float* __restrict__ W, __nv_bfloat16* __restrict__ dst,
                       int R, int K)
{
    int e = blockIdx.x * 256 + threadIdx.x;
    if (e >= R * K) return;
    int r = e / K, k = e - r * K;
    float v = W[e];
    int rt = r >> 7, rr = r & 127, kc = k >> 5, kk = k & 31;
    size_t base = (size_t)(rt * (K >> 5) + kc) * 10240 + rr * 40 + kk;
    __nv_bfloat16 h = __float2bfloat16(v);
    dst[base]        = h;
    dst[base + 5120] = __float2bfloat16(v - __bfloat162float(h));
}

// ---------------- K/V projections (batch-invariant, tiny) ----------------
__global__ void kv_proj(const float* __restrict__ wk, const float* __restrict__ bk,
                        const float* __restrict__ wv, const float* __restrict__ bv,
                        const float* __restrict__ bcw)
{
    __shared__ float bs[C_];
    int m = blockIdx.x, o = threadIdx.x;
    bs[o] = bcw[m * C_ + o];
    __syncthreads();
    float ak = bk[o], av = bv[o];
    const float* wkr = wk + (size_t)o * C_;
    const float* wvr = wv + (size_t)o * C_;
#pragma unroll 8
    for (int c = 0; c < C_; c++) {
        ak = fmaf(wkr[c], bs[c], ak);
        av = fmaf(wvr[c], bs[c], av);
    }
    g_kp[o * M_ + m] = ak;
    g_vp[o * M_ + m] = av;
}

// ---------------- HMMA split-bf16 GEMM: Y = act(W @ X + bias [+resid]) ----------------
// W pre-tiled (wblk). X, Y, resid: fp32 [B][K or R][NPIX].
// CTA: 128 rows x 128 pixels. 8 warps = 2(m) x 4(n); warp tile 64x32.
// smem (dynamic 57344B): Whi@0, Wlo@10240, Xhi@20480, Xlo@30720, stage fp32@40960 (16KB)
__global__ __launch_bounds__(256, 2)
void hgemm(const __nv_bfloat16* __restrict__ wblk, const float* __restrict__ X,
           const float* __restrict__ bias, const float* __restrict__ resid,
           float* __restrict__ Y, int R, int K, int act)
{
    extern __shared__ char sm[];
    float* stage = (float*)(sm + 40960);          // [32 k][128 n]
    const int tid  = threadIdx.x;
    const int lane = tid & 31, wid = tid >> 5;
    const int wm = wid & 1, wn = wid >> 1;
    const int n0g = blockIdx.x * 128;             // NPIX%128==0 -> never crosses batch
    const int b   = n0g / NPIX;
    const int nn  = n0g - b * NPIX;
    const int rt  = blockIdx.y;
    const int KCH = K >> 5;

    const uint32_t sb = (uint32_t)__cvta_generic_to_shared(sm);

    float acc[4][4][4];
#pragma unroll
    for (int i = 0; i < 4; i++)
#pragma unroll
        for (int j = 0; j < 4; j++)
#pragma unroll
            for (int q = 0; q < 4; q++) acc[i][j][q] = 0.0f;

    const float* Xb = X + (size_t)b * K * NPIX + nn;
    const int sp = tid & 127;     // pixel handled in convert phase
    const int kh = tid >> 7;      // k-half (0/1)

    for (int kc = 0; kc < KCH; kc++) {
        // ---- W chunk: contiguous copy of pre-tiled hi+lo block (20480 B)
        const uint4* ws = (const uint4*)(wblk + (size_t)(rt * KCH + kc) * 10240);
        uint4* wd = (uint4*)sm;
#pragma unroll
        for (int i = 0; i < 5; i++) wd[tid + i * 256] = ws[tid + i * 256];
        // ---- stage X fp32 [32][128], coalesced along pixels
        const float* Xc = Xb + (size_t)(kc * 32) * NPIX;
#pragma unroll
        for (int i = 0; i < 16; i++)
            stage[(kh + i * 2) * 128 + sp] = Xc[(size_t)(kh + i * 2) * NPIX + sp];
        __syncthreads();
        // ---- split + transpose into [n][k] bf16 planes (thread = pixel, 16 k's)
        {
            uint32_t hv[8], lv[8];
#pragma unroll
            for (int j = 0; j < 8; j++) {
                float v0 = stage[(kh * 16 + 2 * j    ) * 128 + sp];
                float v1 = stage[(kh * 16 + 2 * j + 1) * 128 + sp];
                __nv_bfloat16 h0 = __float2bfloat16(v0), h1 = __float2bfloat16(v1);
                __nv_bfloat16 l0 = __float2bfloat16(v0 - __bfloat162float(h0));
                __nv_bfloat16 l1 = __float2bfloat16(v1 - __bfloat162float(h1));
                hv[j] = (uint32_t)__bfloat16_as_ushort(h0) | ((uint32_t)__bfloat16_as_ushort(h1) << 16);
                lv[j] = (uint32_t)__bfloat16_as_ushort(l0) | ((uint32_t)__bfloat16_as_ushort(l1) << 16);
            }
            uint32_t* xh = (uint32_t*)(sm + 20480) + sp * 20 + kh * 8;
            uint32_t* xl = (uint32_t*)(sm + 30720) + sp * 20 + kh * 8;
            *(uint4*)(xh)     = make_uint4(hv[0], hv[1], hv[2], hv[3]);
            *(uint4*)(xh + 4) = make_uint4(hv[4], hv[5], hv[6], hv[7]);
            *(uint4*)(xl)     = make_uint4(lv[0], lv[1], lv[2], lv[3]);
            *(uint4*)(xl + 4) = make_uint4(lv[4], lv[5], lv[6], lv[7]);
        }
        __syncthreads();

        // ---- 2 x k16 MMA steps
#pragma unroll
        for (int ks = 0; ks < 2; ks++) {
            const int ko = ks * 16;
            uint32_t bh[4][2], bl[4][2];
#pragma unroll
            for (int nt = 0; nt < 4; nt++) {
                int rowB = wn * 32 + nt * 8 + (lane & 7);
                int kofB = ko + ((lane >> 3) & 1) * 8;
                uint32_t ab = sb + 20480 + rowB * 80 + kofB * 2;
                ldsm2(bh[nt], ab);
                ldsm2(bl[nt], ab + 10240);
            }
#pragma unroll
            for (int mt = 0; mt < 4; mt++) {
                int rowA = wm * 64 + mt * 16 + (lane & 7) + ((lane >> 3) & 1) * 8;
                int kofA = ko + (lane >> 4) * 8;
                uint32_t aa = sb + rowA * 80 + kofA * 2;
                uint32_t ah[4], al[4];
                ldsm4(ah, aa);
                ldsm4(al, aa + 10240);
#pragma unroll
                for (int nt = 0; nt < 4; nt++) {
                    mma_bf16(acc[mt][nt], ah, bh[nt]);   // hi*hi
                    mma_bf16(acc[mt][nt], ah, bl[nt]);   // hi*lo
                    mma_bf16(acc[mt][nt], al, bh[nt]);   // lo*hi
                }
            }
        }
        __syncthreads();
    }

    // ---- epilogue: bias (+resid) (+relu), fp32 [b][R][NPIX], float2 stores
    const int g = lane >> 2, q = lane & 3;
#pragma unroll
    for (int mt = 0; mt < 4; mt++) {
        int r0 = rt * 128 + wm * 64 + mt * 16 + g;
        float b0v = __ldg(bias + r0), b1v = __ldg(bias + r0 + 8);
#pragma unroll
        for (int nt = 0; nt < 4; nt++) {
            int ncol = wn * 32 + nt * 8 + 2 * q;
            size_t off0 = ((size_t)b * R + r0) * NPIX + nn + ncol;
            size_t off1 = off0 + (size_t)8 * NPIX;
            float2 v0 = make_float2(acc[mt][nt][0] + b0v, acc[mt][nt][1] + b0v);
            float2 v1 = make_float2(acc[mt][nt][2] + b1v, acc[mt][nt][3] + b1v);
            if (resid) {
                float2 ra = *(const float2*)(resid + off0);
                float2 rb = *(const float2*)(resid + off1);
                v0.x += ra.x; v0.y += ra.y; v1.x += rb.x; v1.y += rb.y;
            }
            if (act) {
                v0.x = fmaxf(v0.x, 0.f); v0.y = fmaxf(v0.y, 0.f);
                v1.x = fmaxf(v1.x, 0.f); v1.y = fmaxf(v1.y, 0.f);
            }
            *(float2*)(Y + off0) = v0;
            *(float2*)(Y + off1) = v1;
        }
    }
}

// ---------------- attention (unchanged from validated baseline) ----------------
__global__ __launch_bounds__(128)
void attn_kernel(const float* __restrict__ Q, float* __restrict__ Xout)
{
    __shared__ float kps[DH_][M_];
    __shared__ float vps[DH_][M_];
    const int h   = blockIdx.y;
    const int tid = threadIdx.x;
    for (int i = tid; i < DH_ * M_; i += 128) {
        int d = i >> 6, m = i & 63;
        kps[d][m] = g_kp[(d * NH_ + h) * M_ + m];
        vps[d][m] = g_vp[(d * NH_ + h) * M_ + m];
    }
    __syncthreads();

    const int j = blockIdx.x * 128 + tid;
    const int b = j / NPIX;
    const int n = j - b * NPIX;
    const float* Qb = Q + (size_t)b * C_ * NPIX + n;

    float s[M_];
#pragma unroll
    for (int m = 0; m < M_; m++) s[m] = 0.0f;
#pragma unroll
    for (int d = 0; d < DH_; d++) {
        float qd = Qb[(size_t)(d * NH_ + h) * NPIX];
#pragma unroll
        for (int m = 0; m < M_; m++) s[m] = fmaf(qd, kps[d][m], s[m]);
    }
    float mx = s[0];
#pragma unroll
    for (int m = 1; m < M_; m++) mx = fmaxf(mx, s[m]);
    float ssum = 0.0f;
#pragma unroll
    for (int m = 0; m < M_; m++) {
        float e = fast_exp((s[m] - mx) * 0.17677669529663687f);
        s[m] = e;
        ssum += e;
    }
    float inv = 1.0f / ssum;
    float* Xb = Xout + (size_t)b * C_ * NPIX + n;
#pragma unroll
    for (int d = 0; d < DH_; d++) {
        float acc = 0.0f;
#pragma unroll
        for (int m = 0; m < M_; m++) acc = fmaf(s[m], vps[d][m], acc);
        Xb[(size_t)(d * NH_ + h) * NPIX] = acc * inv;
    }
}

// ---------------- cosine reweighting (unchanged) ----------------
__global__ void cos_kernel(const float* __restrict__ merged, const float* __restrict__ feat,
                           float* __restrict__ out)
{
    const int j = blockIdx.x * 256 + threadIdx.x;
    const int b = j / NPIX;
    const int n = j - b * NPIX;
    const size_t base = (size_t)b * C_ * NPIX + n;
    const float* mc = merged + base;
    const float* fc = feat + base;
    float dot = 0.0f, nm = 0.0f, nf = 0.0f;
#pragma unroll 8
    for (int c = 0; c < C_; c++) {
        float a = mc[(size_t)c * NPIX];
        float f = fc[(size_t)c * NPIX];
        dot = fmaf(a, f, dot);
        nm  = fmaf(a, a, nm);
        nf  = fmaf(f, f, nf);
    }
    float sc = dot / ((sqrtf(nm) + 1e-5f) * (sqrtf(nf) + 1e-5f)) + 1.0f;
    float* oc = out + base;
#pragma unroll 8
    for (int c = 0; c < C_; c++)
        oc[(size_t)c * NPIX] = fc[(size_t)c * NPIX] * sc;
}

// ---------------- LayerNorm (unchanged) ----------------
__global__ void ln_kernel(const float* __restrict__ src, const float* __restrict__ gamma,
                          const float* __restrict__ beta, float* __restrict__ out)
{
    const int j = blockIdx.x * 256 + threadIdx.x;
    const int b = j / NPIX;
    const int n = j - b * NPIX;
    const size_t base = (size_t)b * C_ * NPIX + n;
    const float* sc = src + base;
    float s = 0.0f, s2 = 0.0f;
#pragma unroll 8
    for (int c = 0; c < C_; c++) {
        float v = sc[(size_t)c * NPIX];
        s += v;
        s2 = fmaf(v, v, s2);
    }
    float mu  = s * (1.0f / C_);
    float var = s2 * (1.0f / C_) - mu * mu;
    float inv = rsqrtf(var + 1e-5f);
    float* oc = out + base;
#pragma unroll 8
    for (int c = 0; c < C_; c++)
        oc[(size_t)c * NPIX] = (sc[(size_t)c * NPIX] - mu) * inv * gamma[c] + beta[c];
}

// ---------------- host orchestration ----------------
extern "C" void kernel_launch(void* const* d_in, const int* in_sizes, int n_in,
                              void* d_out, int out_size)
{
    const float* feature = (const float*)d_in[0];
    const float* bcw     = (const float*)d_in[1];
    const float* wq      = (const float*)d_in[2];
    const float* bq      = (const float*)d_in[3];
    const float* wk      = (const float*)d_in[4];
    const float* bk      = (const float*)d_in[5];
    const float* wv      = (const float*)d_in[6];
    const float* bv      = (const float*)d_in[7];
    const float* wm      = (const float*)d_in[8];
    const float* bm      = (const float*)d_in[9];
    const float* w1      = (const float*)d_in[10];
    const float* b1      = (const float*)d_in[11];
    const float* w2      = (const float*)d_in[12];
    const float* b2      = (const float*)d_in[13];
    const float* gamma   = (const float*)d_in[14];
    const float* beta    = (const float*)d_in[15];
    float* out = (float*)d_out;

    float *pQ, *pX, *pO, *pH1;
    __nv_bfloat16 *pwqb, *pwmb, *pw1b, *pw2b;
    cudaGetSymbolAddress((void**)&pQ,   g_Q);
    cudaGetSymbolAddress((void**)&pX,   g_X);
    cudaGetSymbolAddress((void**)&pO,   g_O);
    cudaGetSymbolAddress((void**)&pH1,  g_H1);
    cudaGetSymbolAddress((void**)&pwqb, g_wqb);
    cudaGetSymbolAddress((void**)&pwmb, g_wmb);
    cudaGetSymbolAddress((void**)&pw1b, g_w1b);
    cudaGetSymbolAddress((void**)&pw2b, g_w2b);

    const int SMEM = 57344;
    cudaFuncSetAttribute(hgemm, cudaFuncAttributeMaxDynamicSharedMemorySize, SMEM);

    // weight prep (tiny, deterministic; reruns each call)
    wsplit<<<256, 256>>>(wq, pwqb, 256, 256);
    wsplit<<<256, 256>>>(wm, pwmb, 256, 256);
    wsplit<<<512, 256>>>(w1, pw1b, 512, 256);
    wsplit<<<512, 256>>>(w2, pw2b, 256, 512);

    // K/V projections (batch-invariant)
    kv_proj<<<M_, C_>>>(wk, bk, wv, bv, bcw);

    const int GX = BN_TOT / 128;   // 1152

    // Q = wq @ feat + bq
    hgemm<<<dim3(GX, 2), 256, SMEM>>>(pwqb, feature, bq, nullptr, pQ, 256, 256, 0);
    // attention
    attn_kernel<<<dim3(BN_TOT / 128, NH_), 128>>>(pQ, pX);
    // merged = wm @ X + bm  (overwrites g_Q)
    hgemm<<<dim3(GX, 2), 256, SMEM>>>(pwmb, pX, bm, nullptr, pQ, 256, 256, 0);
    // cosine reweight
    cos_kernel<<<BN_TOT / 256, 256>>>(pQ, feature, pO);
    // H1 = relu(w1 @ out + b1)
    hgemm<<<dim3(GX, 4), 256, SMEM>>>(pw1b, pO, b1, nullptr, pH1, 512, 256, 1);
    // src = out + w2 @ H1 + b2  (into g_X)
    hgemm<<<dim3(GX, 2), 256, SMEM>>>(pw2b, pH1, b2, pO, pX, 256, 512, 0);
    // LayerNorm -> final output
    ln_kernel<<<BN_TOT / 256, 256>>>(pX, gamma, beta, out);
}

// round 10
// speedup vs baseline: 3.0148x; 1.0774x over previous
#include <cuda_runtime.h>
#include <cuda_bf16.h>
#include <math.h>
#include <stdint.h>

// ---------------- problem constants ----------------
#define B_    64
#define C_    256
#define NPIX  2304          // 48*48
#define BN_TOT (B_ * NPIX)  // 147456 pixels
#define NH_   8
#define DH_   32
#define M_    64
#define DFF_  512

// ---------------- scratch (__device__ globals; no allocs allowed) ----------------
__device__ float g_kp[C_ * M_];
__device__ float g_vp[C_ * M_];
__device__ float g_Q [(size_t)B_ * C_  * NPIX];
__device__ float g_X [(size_t)B_ * C_  * NPIX];
__device__ float g_O [(size_t)B_ * C_  * NPIX];
__device__ float g_H1[(size_t)B_ * DFF_ * NPIX];
// pre-split + pre-tiled weight blocks, per (rowtile rt, kchunk kc of 16):
//   6144 bf16 = [hi: 128 rows x 24 (16 used)][lo: same], rows 48B (16B-aligned, ldsm-conflict-free)
__device__ __align__(16) __nv_bfloat16 g_wqb[(size_t)2 * 16 * 6144];
__device__ __align__(16) __nv_bfloat16 g_wmb[(size_t)2 * 16 * 6144];
__device__ __align__(16) __nv_bfloat16 g_w1b[(size_t)4 * 16 * 6144];
__device__ __align__(16) __nv_bfloat16 g_w2b[(size_t)2 * 32 * 6144];

// ---------------- fast exp on the FMA pipe ----------------
__device__ __forceinline__ float fast_exp(float x) {
    x = fmaxf(x, -80.0f);
    float y  = x * 1.4426950408889634f;
    float fk = floorf(y);
    float f  = y - fk;
    float p  = 1.5398e-4f;
    p = fmaf(p, f, 1.3333558e-3f);
    p = fmaf(p, f, 9.6181291e-3f);
    p = fmaf(p, f, 5.5504109e-2f);
    p = fmaf(p, f, 2.4022651e-1f);
    p = fmaf(p, f, 6.9314718e-1f);
    p = fmaf(p, f, 1.0f);
    return __int_as_float(((int)fk + 127) << 23) * p;
}

// ---------------- mma / ldmatrix / cp.async helpers ----------------
__device__ __forceinline__ void mma_bf16(float* d, const uint32_t* a, const uint32_t* b) {
    asm volatile("mma.sync.aligned.m16n8k16.row.col.f32.bf16.bf16.f32 "
        "{%0,%1,%2,%3}, {%4,%5,%6,%7}, {%8,%9}, {%0,%1,%2,%3};"
        : "+f"(d[0]), "+f"(d[1]), "+f"(d[2]), "+f"(d[3])
        : "r"(a[0]), "r"(a[1]), "r"(a[2]), "r"(a[3]), "r"(b[0]), "r"(b[1]));
}
__device__ __forceinline__ void ldsm4(uint32_t* r, uint32_t addr) {
    asm volatile("ldmatrix.sync.aligned.m8n8.x4.shared.b16 {%0,%1,%2,%3}, [%4];"
        : "=r"(r[0]), "=r"(r[1]), "=r"(r[2]), "=r"(r[3]) : "r"(addr));
}
__device__ __forceinline__ void ldsm2(uint32_t* r, uint32_t addr) {
    asm volatile("ldmatrix.sync.aligned.m8n8.x2.shared.b16 {%0,%1}, [%2];"
        : "=r"(r[0]), "=r"(r[1]) : "r"(addr));
}
__device__ __forceinline__ void cp16(uint32_t dst, const void* src) {
    asm volatile("cp.async.cg.shared.global [%0], [%1], 16;" :: "r"(dst), "l"(src) : "memory");
}
#define CP_COMMIT() asm volatile("cp.async.commit_group;" ::: "memory")
#define CP_WAIT0()  asm volatile("cp.async.wait_group 0;" ::: "memory")

// ---------------- weight split/tiling prep (tiny, rerun every call) ----------------
__global__ void wsplit(const float* __restrict__ W, __nv_bfloat16* __restrict__ dst,
                       int R, int K)
{
    int e = blockIdx.x * 256 + threadIdx.x;
    if (e >= R * K) return;
    int r = e / K, k = e - r * K;
    float v = W[e];
    int rt = r >> 7, rr = r & 127, kc = k >> 4, kk = k & 15;
    size_t base = (size_t)(rt * (K >> 4) + kc) * 6144 + rr * 24 + kk;
    __nv_bfloat16 h = __float2bfloat16(v);
    dst[base]        = h;
    dst[base + 3072] = __float2bfloat16(v - __bfloat162float(h));
}

// ---------------- K/V projections (batch-invariant, tiny) ----------------
__global__ void kv_proj(const float* __restrict__ wk, const float* __restrict__ bk,
                        const float* __restrict__ wv, const float* __restrict__ bv,
                        const float* __restrict__ bcw)
{
    __shared__ float bs[C_];
    int m = blockIdx.x, o = threadIdx.x;
    bs[o] = bcw[m * C_ + o];
    __syncthreads();
    float ak = bk[o], av = bv[o];
    const float* wkr = wk + (size_t)o * C_;
    const float* wvr = wv + (size_t)o * C_;
#pragma unroll 8
    for (int c = 0; c < C_; c++) {
        ak = fmaf(wkr[c], bs[c], ak);
        av = fmaf(wvr[c], bs[c], av);
    }
    g_kp[o * M_ + m] = ak;
    g_vp[o * M_ + m] = av;
}

// ---------------- pipelined HMMA split-bf16 GEMM ----------------
// Y = act(W @ X + bias [+resid]).  W pre-tiled. X/Y/resid fp32 [B][K|R][NPIX].
// CTA 128 rows x 128 px, 8 warps (2m x 4n). Kc=16 chunks.
// smem (86016B): W ring x3 @0 (12288 ea), fp32 stage ring x3 @36864 (8192 ea),
//                bf16 planes x2 @61440 (12288 ea: hi 6144 | lo 6144)
__global__ __launch_bounds__(256, 2)
void hgemm(const __nv_bfloat16* __restrict__ wblk, const float* __restrict__ X,
           const float* __restrict__ bias, const float* __restrict__ resid,
           float* __restrict__ Y, int R, int K, int act)
{
    extern __shared__ char sm[];
    const int tid  = threadIdx.x;
    const int lane = tid & 31, wid = tid >> 5;
    const int wm = wid & 1, wn = wid >> 1;
    const int n0g = blockIdx.x * 128;            // NPIX%128==0 -> never crosses batch
    const int b   = n0g / NPIX;
    const int nn  = n0g - b * NPIX;
    const int rt  = blockIdx.y;
    const int KCH = K >> 4;
    const uint32_t sb = (uint32_t)__cvta_generic_to_shared(sm);
    const float* Xb = X + (size_t)b * K * NPIX + nn;
    const int sp = tid & 127, kh = tid >> 7;

    float acc[4][4][4];
#pragma unroll
    for (int i = 0; i < 4; i++)
#pragma unroll
        for (int j = 0; j < 4; j++)
#pragma unroll
            for (int q = 0; q < 4; q++) acc[i][j][q] = 0.0f;

    // ---- async loader: chunk kc -> ring slot kc%3 (W 12288B + stage 8192B)
    auto load_chunk = [&](int kc) {
        const int bi = kc % 3;
        const uint4* ws = (const uint4*)(wblk + (size_t)(rt * KCH + kc) * 6144);
        const uint32_t wdst = sb + bi * 12288;
#pragma unroll
        for (int j = 0; j < 3; j++)
            cp16(wdst + (tid + j * 256) * 16, ws + tid + j * 256);
        const float* Xc = Xb + (size_t)(kc * 16) * NPIX;
        const uint32_t sdst = sb + 36864 + bi * 8192;
#pragma unroll
        for (int j = 0; j < 2; j++) {
            int u = tid + j * 256;
            int k = u >> 5, n4 = u & 31;
            cp16(sdst + u * 16, Xc + (size_t)k * NPIX + n4 * 4);
        }
        CP_COMMIT();
    };

    // ---- split fp32 stage -> bf16 hi/lo planes (thread = pixel sp, k-half kh)
    auto convert = [&](int kc) {
        const float* stg = (const float*)(sm + 36864 + (kc % 3) * 8192);
        char* pl = sm + 61440 + (kc & 1) * 12288;
        uint32_t hv[4], lv[4];
#pragma unroll
        for (int j = 0; j < 4; j++) {
            float v0 = stg[(kh * 8 + 2 * j    ) * 128 + sp];
            float v1 = stg[(kh * 8 + 2 * j + 1) * 128 + sp];
            __nv_bfloat16 h0 = __float2bfloat16(v0), h1 = __float2bfloat16(v1);
            __nv_bfloat16 l0 = __float2bfloat16(v0 - __bfloat162float(h0));
            __nv_bfloat16 l1 = __float2bfloat16(v1 - __bfloat162float(h1));
            hv[j] = (uint32_t)__bfloat16_as_ushort(h0) | ((uint32_t)__bfloat16_as_ushort(h1) << 16);
            lv[j] = (uint32_t)__bfloat16_as_ushort(l0) | ((uint32_t)__bfloat16_as_ushort(l1) << 16);
        }
        *(uint4*)(pl +        sp * 48 + kh * 16) = make_uint4(hv[0], hv[1], hv[2], hv[3]);
        *(uint4*)(pl + 6144 + sp * 48 + kh * 16) = make_uint4(lv[0], lv[1], lv[2], lv[3]);
    };

    // ---- 3-term HMMA on one chunk
    auto do_mma = [&](int kc) {
        const uint32_t sbW = sb + (kc % 3) * 12288;
        const uint32_t sbX = sb + 61440 + (kc & 1) * 12288;
        uint32_t bh[4][2], bl[4][2];
#pragma unroll
        for (int nt = 0; nt < 4; nt++) {
            int rowB = wn * 32 + nt * 8 + (lane & 7);
            int kofB = ((lane >> 3) & 1) * 8;
            uint32_t ab = sbX + rowB * 48 + kofB * 2;
            ldsm2(bh[nt], ab);
            ldsm2(bl[nt], ab + 6144);
        }
#pragma unroll
        for (int mt = 0; mt < 4; mt++) {
            int rowA = wm * 64 + mt * 16 + (lane & 7) + ((lane >> 3) & 1) * 8;
            int kofA = (lane >> 4) * 8;
            uint32_t aa = sbW + rowA * 48 + kofA * 2;
            uint32_t ah[4], al[4];
            ldsm4(ah, aa);
            ldsm4(al, aa + 6144);
#pragma unroll
            for (int nt = 0; nt < 4; nt++) {
                mma_bf16(acc[mt][nt], ah, bh[nt]);   // hi*hi
                mma_bf16(acc[mt][nt], ah, bl[nt]);   // hi*lo
                mma_bf16(acc[mt][nt], al, bh[nt]);   // lo*hi
            }
        }
    };

    // ---- pipeline: loads 2 ahead; convert(kc+1) overlaps mma(kc)
    load_chunk(0);
    if (KCH > 1) load_chunk(1);
    CP_WAIT0();
    __syncthreads();
    convert(0);
    for (int kc = 0; kc < KCH; kc++) {
        __syncthreads();                       // planes[kc&1] visible; ring slot for kc+2 free
        if (kc + 2 < KCH) load_chunk(kc + 2);  // async, flies under mma+convert
        do_mma(kc);
        if (kc + 1 < KCH) convert(kc + 1);     // fills FMA/LSU pipes while HMMA runs
        CP_WAIT0();                            // chunk kc+2 arrived by next iteration
    }

    // ---- epilogue: bias (+resid) (+relu), fp32 [b][R][NPIX], float2 stores
    const int g = lane >> 2, q = lane & 3;
#pragma unroll
    for (int mt = 0; mt < 4; mt++) {
        int r0 = rt * 128 + wm * 64 + mt * 16 + g;
        float b0v = __ldg(bias + r0), b1v = __ldg(bias + r0 + 8);
#pragma unroll
        for (int nt = 0; nt < 4; nt++) {
            int ncol = wn * 32 + nt * 8 + 2 * q;
            size_t off0 = ((size_t)b * R + r0) * NPIX + nn + ncol;
            size_t off1 = off0 + (size_t)8 * NPIX;
            float2 v0 = make_float2(acc[mt][nt][0] + b0v, acc[mt][nt][1] + b0v);
            float2 v1 = make_float2(acc[mt][nt][2] + b1v, acc[mt][nt][3] + b1v);
            if (resid) {
                float2 ra = *(const float2*)(resid + off0);
                float2 rb = *(const float2*)(resid + off1);
                v0.x += ra.x; v0.y += ra.y; v1.x += rb.x; v1.y += rb.y;
            }
            if (act) {
                v0.x = fmaxf(v0.x, 0.f); v0.y = fmaxf(v0.y, 0.f);
                v1.x = fmaxf(v1.x, 0.f); v1.y = fmaxf(v1.y, 0.f);
            }
            *(float2*)(Y + off0) = v0;
            *(float2*)(Y + off1) = v1;
        }
    }
}

// ---------------- attention (unchanged, validated) ----------------
__global__ __launch_bounds__(128)
void attn_kernel(const float* __restrict__ Q, float* __restrict__ Xout)
{
    __shared__ float kps[DH_][M_];
    __shared__ float vps[DH_][M_];
    const int h   = blockIdx.y;
    const int tid = threadIdx.x;
    for (int i = tid; i < DH_ * M_; i += 128) {
        int d = i >> 6, m = i & 63;
        kps[d][m] = g_kp[(d * NH_ + h) * M_ + m];
        vps[d][m] = g_vp[(d * NH_ + h) * M_ + m];
    }
    __syncthreads();

    const int j = blockIdx.x * 128 + tid;
    const int b = j / NPIX;
    const int n = j - b * NPIX;
    const float* Qb = Q + (size_t)b * C_ * NPIX + n;

    float s[M_];
#pragma unroll
    for (int m = 0; m < M_; m++) s[m] = 0.0f;
#pragma unroll
    for (int d = 0; d < DH_; d++) {
        float qd = Qb[(size_t)(d * NH_ + h) * NPIX];
#pragma unroll
        for (int m = 0; m < M_; m++) s[m] = fmaf(qd, kps[d][m], s[m]);
    }
    float mx = s[0];
#pragma unroll
    for (int m = 1; m < M_; m++) mx = fmaxf(mx, s[m]);
    float ssum = 0.0f;
#pragma unroll
    for (int m = 0; m < M_; m++) {
        float e = fast_exp((s[m] - mx) * 0.17677669529663687f);
        s[m] = e;
        ssum += e;
    }
    float inv = 1.0f / ssum;
    float* Xb = Xout + (size_t)b * C_ * NPIX + n;
#pragma unroll
    for (int d = 0; d < DH_; d++) {
        float acc = 0.0f;
#pragma unroll
        for (int m = 0; m < M_; m++) acc = fmaf(s[m], vps[d][m], acc);
        Xb[(size_t)(d * NH_ + h) * NPIX] = acc * inv;
    }
}

// ---------------- cosine reweighting (unchanged) ----------------
__global__ void cos_kernel(const float* __restrict__ merged, const float* __restrict__ feat,
                           float* __restrict__ out)
{
    const int j = blockIdx.x * 256 + threadIdx.x;
    const int b = j / NPIX;
    const int n = j - b * NPIX;
    const size_t base = (size_t)b * C_ * NPIX + n;
    const float* mc = merged + base;
    const float* fc = feat + base;
    float dot = 0.0f, nm = 0.0f, nf = 0.0f;
#pragma unroll 8
    for (int c = 0; c < C_; c++) {
        float a = mc[(size_t)c * NPIX];
        float f = fc[(size_t)c * NPIX];
        dot = fmaf(a, f, dot);
        nm  = fmaf(a, a, nm);
        nf  = fmaf(f, f, nf);
    }
    float sc = dot / ((sqrtf(nm) + 1e-5f) * (sqrtf(nf) + 1e-5f)) + 1.0f;
    float* oc = out + base;
#pragma unroll 8
    for (int c = 0; c < C_; c++)
        oc[(size_t)c * NPIX] = fc[(size_t)c * NPIX] * sc;
}

// ---------------- LayerNorm (unchanged) ----------------
__global__ void ln_kernel(const float* __restrict__ src, const float* __restrict__ gamma,
                          const float* __restrict__ beta, float* __restrict__ out)
{
    const int j = blockIdx.x * 256 + threadIdx.x;
    const int b = j / NPIX;
    const int n = j - b * NPIX;
    const size_t base = (size_t)b * C_ * NPIX + n;
    const float* sc = src + base;
    float s = 0.0f, s2 = 0.0f;
#pragma unroll 8
    for (int c = 0; c < C_; c++) {
        float v = sc[(size_t)c * NPIX];
        s += v;
        s2 = fmaf(v, v, s2);
    }
    float mu  = s * (1.0f / C_);
    float var = s2 * (1.0f / C_) - mu * mu;
    float inv = rsqrtf(var + 1e-5f);
    float* oc = out + base;
#pragma unroll 8
    for (int c = 0; c < C_; c++)
        oc[(size_t)c * NPIX] = (sc[(size_t)c * NPIX] - mu) * inv * gamma[c] + beta[c];
}

// ---------------- host orchestration ----------------
extern "C" void kernel_launch(void* const* d_in, const int* in_sizes, int n_in,
                              void* d_out, int out_size)
{
    const float* feature = (const float*)d_in[0];
    const float* bcw     = (const float*)d_in[1];
    const float* wq      = (const float*)d_in[2];
    const float* bq      = (const float*)d_in[3];
    const float* wk      = (const float*)d_in[4];
    const float* bk      = (const float*)d_in[5];
    const float* wv      = (const float*)d_in[6];
    const float* bv      = (const float*)d_in[7];
    const float* wm      = (const float*)d_in[8];
    const float* bm      = (const float*)d_in[9];
    const float* w1      = (const float*)d_in[10];
    const float* b1      = (const float*)d_in[11];
    const float* w2      = (const float*)d_in[12];
    const float* b2      = (const float*)d_in[13];
    const float* gamma   = (const float*)d_in[14];
    const float* beta    = (const float*)d_in[15];
    float* out = (float*)d_out;

    float *pQ, *pX, *pO, *pH1;
    __nv_bfloat16 *pwqb, *pwmb, *pw1b, *pw2b;
    cudaGetSymbolAddress((void**)&pQ,   g_Q);
    cudaGetSymbolAddress((void**)&pX,   g_X);
    cudaGetSymbolAddress((void**)&pO,   g_O);
    cudaGetSymbolAddress((void**)&pH1,  g_H1);
    cudaGetSymbolAddress((void**)&pwqb, g_wqb);
    cudaGetSymbolAddress((void**)&pwmb, g_wmb);
    cudaGetSymbolAddress((void**)&pw1b, g_w1b);
    cudaGetSymbolAddress((void**)&pw2b, g_w2b);

    const int SMEM = 86016;
    cudaFuncSetAttribute(hgemm, cudaFuncAttributeMaxDynamicSharedMemorySize, SMEM);

    // weight prep (tiny, deterministic; reruns each call)
    wsplit<<<256, 256>>>(wq, pwqb, 256, 256);
    wsplit<<<256, 256>>>(wm, pwmb, 256, 256);
    wsplit<<<512, 256>>>(w1, pw1b, 512, 256);
    wsplit<<<512, 256>>>(w2, pw2b, 256, 512);

    // K/V projections (batch-invariant)
    kv_proj<<<M_, C_>>>(wk, bk, wv, bv, bcw);

    const int GX = BN_TOT / 128;   // 1152

    // Q = wq @ feat + bq
    hgemm<<<dim3(GX, 2), 256, SMEM>>>(pwqb, feature, bq, nullptr, pQ, 256, 256, 0);
    // attention
    attn_kernel<<<dim3(BN_TOT / 128, NH_), 128>>>(pQ, pX);
    // merged = wm @ X + bm  (overwrites g_Q)
    hgemm<<<dim3(GX, 2), 256, SMEM>>>(pwmb, pX, bm, nullptr, pQ, 256, 256, 0);
    // cosine reweight
    cos_kernel<<<BN_TOT / 256, 256>>>(pQ, feature, pO);
    // H1 = relu(w1 @ out + b1)
    hgemm<<<dim3(GX, 4), 256, SMEM>>>(pw1b, pO, b1, nullptr, pH1, 512, 256, 1);
    // src = out + w2 @ H1 + b2  (into g_X)
    hgemm<<<dim3(GX, 2), 256, SMEM>>>(pw2b, pH1, b2, pO, pX, 256, 512, 0);
    // LayerNorm -> final output
    ln_kernel<<<BN_TOT / 256, 256>>>(pX, gamma, beta, out);
}

// round 11
// speedup vs baseline: 3.0231x; 1.0028x over previous
#include <cuda_runtime.h>
#include <cuda_bf16.h>
#include <math.h>
#include <stdint.h>

// ---------------- problem constants ----------------
#define B_    64
#define C_    256
#define NPIX  2304          // 48*48
#define BN_TOT (B_ * NPIX)  // 147456 pixels
#define NH_   8
#define DH_   32
#define M_    64
#define DFF_  512

// ---------------- scratch (__device__ globals; no allocs allowed) ----------------
__device__ float g_kp[C_ * M_];
__device__ float g_vp[C_ * M_];
__device__ float g_Q [(size_t)B_ * C_  * NPIX];
__device__ float g_X [(size_t)B_ * C_  * NPIX];
__device__ float g_O [(size_t)B_ * C_  * NPIX];
__device__ float g_H1[(size_t)B_ * DFF_ * NPIX];
// pre-split + pre-tiled weight blocks, per (rowtile rt, kchunk kc of 16):
//   6144 bf16 = [hi: 128 rows x 24 (16 used)][lo: same], rows 48B (16B-aligned, ldsm-conflict-free)
__device__ __align__(16) __nv_bfloat16 g_wqb[(size_t)2 * 16 * 6144];
__device__ __align__(16) __nv_bfloat16 g_wmb[(size_t)2 * 16 * 6144];
__device__ __align__(16) __nv_bfloat16 g_w1b[(size_t)4 * 16 * 6144];
__device__ __align__(16) __nv_bfloat16 g_w2b[(size_t)2 * 32 * 6144];

// ---------------- fast exp on the FMA pipe ----------------
__device__ __forceinline__ float fast_exp(float x) {
    x = fmaxf(x, -80.0f);
    float y  = x * 1.4426950408889634f;
    float fk = floorf(y);
    float f  = y - fk;
    float p  = 1.5398e-4f;
    p = fmaf(p, f, 1.3333558e-3f);
    p = fmaf(p, f, 9.6181291e-3f);
    p = fmaf(p, f, 5.5504109e-2f);
    p = fmaf(p, f, 2.4022651e-1f);
    p = fmaf(p, f, 6.9314718e-1f);
    p = fmaf(p, f, 1.0f);
    return __int_as_float(((int)fk + 127) << 23) * p;
}

// ---------------- mma / ldmatrix / cp.async helpers ----------------
__device__ __forceinline__ void mma_bf16(float* d, const uint32_t* a, const uint32_t* b) {
    asm volatile("mma.sync.aligned.m16n8k16.row.col.f32.bf16.bf16.f32 "
        "{%0,%1,%2,%3}, {%4,%5,%6,%7}, {%8,%9}, {%0,%1,%2,%3};"
        : "+f"(d[0]), "+f"(d[1]), "+f"(d[2]), "+f"(d[3])
        : "r"(a[0]), "r"(a[1]), "r"(a[2]), "r"(a[3]), "r"(b[0]), "r"(b[1]));
}
__device__ __forceinline__ void ldsm4(uint32_t* r, uint32_t addr) {
    asm volatile("ldmatrix.sync.aligned.m8n8.x4.shared.b16 {%0,%1,%2,%3}, [%4];"
        : "=r"(r[0]), "=r"(r[1]), "=r"(r[2]), "=r"(r[3]) : "r"(addr));
}
__device__ __forceinline__ void ldsm2(uint32_t* r, uint32_t addr) {
    asm volatile("ldmatrix.sync.aligned.m8n8.x2.shared.b16 {%0,%1}, [%2];"
        : "=r"(r[0]), "=r"(r[1]) : "r"(addr));
}
__device__ __forceinline__ void cp16(uint32_t dst, const void* src) {
    asm volatile("cp.async.cg.shared.global [%0], [%1], 16;" :: "r"(dst), "l"(src) : "memory");
}
#define CP_COMMIT() asm volatile("cp.async.commit_group;" ::: "memory")
#define CP_WAIT0()  asm volatile("cp.async.wait_group 0;" ::: "memory")

// ---------------- weight split/tiling prep (tiny, rerun every call) ----------------
__global__ void wsplit(const float* __restrict__ W, __nv_bfloat16* __restrict__ dst,
                       int R, int K)
{
    int e = blockIdx.x * 256 + threadIdx.x;
    if (e >= R * K) return;
    int r = e / K, k = e - r * K;
    float v = W[e];
    int rt = r >> 7, rr = r & 127, kc = k >> 4, kk = k & 15;
    size_t base = (size_t)(rt * (K >> 4) + kc) * 6144 + rr * 24 + kk;
    __nv_bfloat16 h = __float2bfloat16(v);
    dst[base]        = h;
    dst[base + 3072] = __float2bfloat16(v - __bfloat162float(h));
}

// ---------------- K/V projections (batch-invariant, tiny) ----------------
__global__ void kv_proj(const float* __restrict__ wk, const float* __restrict__ bk,
                        const float* __restrict__ wv, const float* __restrict__ bv,
                        const float* __restrict__ bcw)
{
    __shared__ float bs[C_];
    int m = blockIdx.x, o = threadIdx.x;
    bs[o] = bcw[m * C_ + o];
    __syncthreads();
    float ak = bk[o], av = bv[o];
    const float* wkr = wk + (size_t)o * C_;
    const float* wvr = wv + (size_t)o * C_;
#pragma unroll 8
    for (int c = 0; c < C_; c++) {
        ak = fmaf(wkr[c], bs[c], ak);
        av = fmaf(wvr[c], bs[c], av);
    }
    g_kp[o * M_ + m] = ak;
    g_vp[o * M_ + m] = av;
}

// ---------------- pipelined HMMA split-bf16 GEMM ----------------
// Y = act(W @ X + bias [+resid]).  W pre-tiled. X/Y/resid fp32 [B][K|R][NPIX].
// CTA 128 rows x 128 px, 8 warps (2m x 4n). Kc=16 chunks.
// smem (86016B): W ring x3 @0 (12288 ea), fp32 stage ring x3 @36864 (8192 ea),
//                bf16 planes x2 @61440 (12288 ea: hi 6144 | lo 6144)
__global__ __launch_bounds__(256, 2)
void hgemm(const __nv_bfloat16* __restrict__ wblk, const float* __restrict__ X,
           const float* __restrict__ bias, const float* __restrict__ resid,
           float* __restrict__ Y, int R, int K, int act)
{
    extern __shared__ char sm[];
    const int tid  = threadIdx.x;
    const int lane = tid & 31, wid = tid >> 5;
    const int wm = wid & 1, wn = wid >> 1;
    const int n0g = blockIdx.x * 128;            // NPIX%128==0 -> never crosses batch
    const int b   = n0g / NPIX;
    const int nn  = n0g - b * NPIX;
    const int rt  = blockIdx.y;
    const int KCH = K >> 4;
    const uint32_t sb = (uint32_t)__cvta_generic_to_shared(sm);
    const float* Xb = X + (size_t)b * K * NPIX + nn;
    const int sp = tid & 127, kh = tid >> 7;

    float acc[4][4][4];
#pragma unroll
    for (int i = 0; i < 4; i++)
#pragma unroll
        for (int j = 0; j < 4; j++)
#pragma unroll
            for (int q = 0; q < 4; q++) acc[i][j][q] = 0.0f;

    // ---- async loader: chunk kc -> ring slot kc%3 (W 12288B + stage 8192B)
    auto load_chunk = [&](int kc) {
        const int bi = kc % 3;
        const uint4* ws = (const uint4*)(wblk + (size_t)(rt * KCH + kc) * 6144);
        const uint32_t wdst = sb + bi * 12288;
#pragma unroll
        for (int j = 0; j < 3; j++)
            cp16(wdst + (tid + j * 256) * 16, ws + tid + j * 256);
        const float* Xc = Xb + (size_t)(kc * 16) * NPIX;
        const uint32_t sdst = sb + 36864 + bi * 8192;
#pragma unroll
        for (int j = 0; j < 2; j++) {
            int u = tid + j * 256;
            int k = u >> 5, n4 = u & 31;
            cp16(sdst + u * 16, Xc + (size_t)k * NPIX + n4 * 4);
        }
        CP_COMMIT();
    };

    // ---- split fp32 stage -> bf16 hi/lo planes (thread = pixel sp, k-half kh)
    auto convert = [&](int kc) {
        const float* stg = (const float*)(sm + 36864 + (kc % 3) * 8192);
        char* pl = sm + 61440 + (kc & 1) * 12288;
        uint32_t hv[4], lv[4];
#pragma unroll
        for (int j = 0; j < 4; j++) {
            float v0 = stg[(kh * 8 + 2 * j    ) * 128 + sp];
            float v1 = stg[(kh * 8 + 2 * j + 1) * 128 + sp];
            __nv_bfloat16 h0 = __float2bfloat16(v0), h1 = __float2bfloat16(v1);
            __nv_bfloat16 l0 = __float2bfloat16(v0 - __bfloat162float(h0));
            __nv_bfloat16 l1 = __float2bfloat16(v1 - __bfloat162float(h1));
            hv[j] = (uint32_t)__bfloat16_as_ushort(h0) | ((uint32_t)__bfloat16_as_ushort(h1) << 16);
            lv[j] = (uint32_t)__bfloat16_as_ushort(l0) | ((uint32_t)__bfloat16_as_ushort(l1) << 16);
        }
        *(uint4*)(pl +        sp * 48 + kh * 16) = make_uint4(hv[0], hv[1], hv[2], hv[3]);
        *(uint4*)(pl + 6144 + sp * 48 + kh * 16) = make_uint4(lv[0], lv[1], lv[2], lv[3]);
    };

    // ---- 3-term HMMA on one chunk
    auto do_mma = [&](int kc) {
        const uint32_t sbW = sb + (kc % 3) * 12288;
        const uint32_t sbX = sb + 61440 + (kc & 1) * 12288;
        uint32_t bh[4][2], bl[4][2];
#pragma unroll
        for (int nt = 0; nt < 4; nt++) {
            int rowB = wn * 32 + nt * 8 + (lane & 7);
            int kofB = ((lane >> 3) & 1) * 8;
            uint32_t ab = sbX + rowB * 48 + kofB * 2;
            ldsm2(bh[nt], ab);
            ldsm2(bl[nt], ab + 6144);
        }
#pragma unroll
        for (int mt = 0; mt < 4; mt++) {
            int rowA = wm * 64 + mt * 16 + (lane & 7) + ((lane >> 3) & 1) * 8;
            int kofA = (lane >> 4) * 8;
            uint32_t aa = sbW + rowA * 48 + kofA * 2;
            uint32_t ah[4], al[4];
            ldsm4(ah, aa);
            ldsm4(al, aa + 6144);
#pragma unroll
            for (int nt = 0; nt < 4; nt++) {
                mma_bf16(acc[mt][nt], ah, bh[nt]);   // hi*hi
                mma_bf16(acc[mt][nt], ah, bl[nt]);   // hi*lo
                mma_bf16(acc[mt][nt], al, bh[nt]);   // lo*hi
            }
        }
    };

    // ---- pipeline: loads 2 ahead; convert(kc+1) overlaps mma(kc)
    load_chunk(0);
    if (KCH > 1) load_chunk(1);
    CP_WAIT0();
    __syncthreads();
    convert(0);
    for (int kc = 0; kc < KCH; kc++) {
        __syncthreads();                       // planes[kc&1] visible; ring slot for kc+2 free
        if (kc + 2 < KCH) load_chunk(kc + 2);  // async, flies under mma+convert
        do_mma(kc);
        if (kc + 1 < KCH) convert(kc + 1);     // fills FMA/LSU pipes while HMMA runs
        CP_WAIT0();                            // chunk kc+2 arrived by next iteration
    }

    // ---- epilogue: bias (+resid) (+relu), fp32 [b][R][NPIX], float2 stores
    const int g = lane >> 2, q = lane & 3;
#pragma unroll
    for (int mt = 0; mt < 4; mt++) {
        int r0 = rt * 128 + wm * 64 + mt * 16 + g;
        float b0v = __ldg(bias + r0), b1v = __ldg(bias + r0 + 8);
#pragma unroll
        for (int nt = 0; nt < 4; nt++) {
            int ncol = wn * 32 + nt * 8 + 2 * q;
            size_t off0 = ((size_t)b * R + r0) * NPIX + nn + ncol;
            size_t off1 = off0 + (size_t)8 * NPIX;
            float2 v0 = make_float2(acc[mt][nt][0] + b0v, acc[mt][nt][1] + b0v);
            float2 v1 = make_float2(acc[mt][nt][2] + b1v, acc[mt][nt][3] + b1v);
            if (resid) {
                float2 ra = *(const float2*)(resid + off0);
                float2 rb = *(const float2*)(resid + off1);
                v0.x += ra.x; v0.y += ra.y; v1.x += rb.x; v1.y += rb.y;
            }
            if (act) {
                v0.x = fmaxf(v0.x, 0.f); v0.y = fmaxf(v0.y, 0.f);
                v1.x = fmaxf(v1.x, 0.f); v1.y = fmaxf(v1.y, 0.f);
            }
            *(float2*)(Y + off0) = v0;
            *(float2*)(Y + off1) = v1;
        }
    }
}

// ---------------- attention (unchanged, validated) ----------------
__global__ __launch_bounds__(128)
void attn_kernel(const float* __restrict__ Q, float* __restrict__ Xout)
{
    __shared__ float kps[DH_][M_];
    __shared__ float vps[DH_][M_];
    const int h   = blockIdx.y;
    const int tid = threadIdx.x;
    for (int i = tid; i < DH_ * M_; i += 128) {
        int d = i >> 6, m = i & 63;
        kps[d][m] = g_kp[(d * NH_ + h) * M_ + m];
        vps[d][m] = g_vp[(d * NH_ + h) * M_ + m];
    }
    __syncthreads();

    const int j = blockIdx.x * 128 + tid;
    const int b = j / NPIX;
    const int n = j - b * NPIX;
    const float* Qb = Q + (size_t)b * C_ * NPIX + n;

    float s[M_];
#pragma unroll
    for (int m = 0; m < M_; m++) s[m] = 0.0f;
#pragma unroll
    for (int d = 0; d < DH_; d++) {
        float qd = Qb[(size_t)(d * NH_ + h) * NPIX];
#pragma unroll
        for (int m = 0; m < M_; m++) s[m] = fmaf(qd, kps[d][m], s[m]);
    }
    float mx = s[0];
#pragma unroll
    for (int m = 1; m < M_; m++) mx = fmaxf(mx, s[m]);
    float ssum = 0.0f;
#pragma unroll
    for (int m = 0; m < M_; m++) {
        float e = fast_exp((s[m] - mx) * 0.17677669529663687f);
        s[m] = e;
        ssum += e;
    }
    float inv = 1.0f / ssum;
    float* Xb = Xout + (size_t)b * C_ * NPIX + n;
#pragma unroll
    for (int d = 0; d < DH_; d++) {
        float acc = 0.0f;
#pragma unroll
        for (int m = 0; m < M_; m++) acc = fmaf(s[m], vps[d][m], acc);
        Xb[(size_t)(d * NH_ + h) * NPIX] = acc * inv;
    }
}

// ---------------- cosine reweighting (unchanged) ----------------
__global__ void cos_kernel(const float* __restrict__ merged, const float* __restrict__ feat,
                           float* __restrict__ out)
{
    const int j = blockIdx.x * 256 + threadIdx.x;
    const int b = j / NPIX;
    const int n = j - b * NPIX;
    const size_t base = (size_t)b * C_ * NPIX + n;
    const float* mc = merged + base;
    const float* fc = feat + base;
    float dot = 0.0f, nm = 0.0f, nf = 0.0f;
#pragma unroll 8
    for (int c = 0; c < C_; c++) {
        float a = mc[(size_t)c * NPIX];
        float f = fc[(size_t)c * NPIX];
        dot = fmaf(a, f, dot);
        nm  = fmaf(a, a, nm);
        nf  = fmaf(f, f, nf);
    }
    float sc = dot / ((sqrtf(nm) + 1e-5f) * (sqrtf(nf) + 1e-5f)) + 1.0f;
    float* oc = out + base;
#pragma unroll 8
    for (int c = 0; c < C_; c++)
        oc[(size_t)c * NPIX] = fc[(size_t)c * NPIX] * sc;
}

// ---------------- LayerNorm (unchanged) ----------------
__global__ void ln_kernel(const float* __restrict__ src, const float* __restrict__ gamma,
                          const float* __restrict__ beta, float* __restrict__ out)
{
    const int j = blockIdx.x * 256 + threadIdx.x;
    const int b = j / NPIX;
    const int n = j - b * NPIX;
    const size_t base = (size_t)b * C_ * NPIX + n;
    const float* sc = src + base;
    float s = 0.0f, s2 = 0.0f;
#pragma unroll 8
    for (int c = 0; c < C_; c++) {
        float v = sc[(size_t)c * NPIX];
        s += v;
        s2 = fmaf(v, v, s2);
    }
    float mu  = s * (1.0f / C_);
    float var = s2 * (1.0f / C_) - mu * mu;
    float inv = rsqrtf(var + 1e-5f);
    float* oc = out + base;
#pragma unroll 8
    for (int c = 0; c < C_; c++)
        oc[(size_t)c * NPIX] = (sc[(size_t)c * NPIX] - mu) * inv * gamma[c] + beta[c];
}

// ---------------- host orchestration ----------------
extern "C" void kernel_launch(void* const* d_in, const int* in_sizes, int n_in,
                              void* d_out, int out_size)
{
    const float* feature = (const float*)d_in[0];
    const float* bcw     = (const float*)d_in[1];
    const float* wq      = (const float*)d_in[2];
    const float* bq      = (const float*)d_in[3];
    const float* wk      = (const float*)d_in[4];
    const float* bk      = (const float*)d_in[5];
    const float* wv      = (const float*)d_in[6];
    const float* bv      = (const float*)d_in[7];
    const float* wm      = (const float*)d_in[8];
    const float* bm      = (const float*)d_in[9];
    const float* w1      = (const float*)d_in[10];
    const float* b1      = (const float*)d_in[11];
    const float* w2      = (const float*)d_in[12];
    const float* b2      = (const float*)d_in[13];
    const float* gamma   = (const float*)d_in[14];
    const float* beta    = (const float*)d_in[15];
    float* out = (float*)d_out;

    float *pQ, *pX, *pO, *pH1;
    __nv_bfloat16 *pwqb, *pwmb, *pw1b, *pw2b;
    cudaGetSymbolAddress((void**)&pQ,   g_Q);
    cudaGetSymbolAddress((void**)&pX,   g_X);
    cudaGetSymbolAddress((void**)&pO,   g_O);
    cudaGetSymbolAddress((void**)&pH1,  g_H1);
    cudaGetSymbolAddress((void**)&pwqb, g_wqb);
    cudaGetSymbolAddress((void**)&pwmb, g_wmb);
    cudaGetSymbolAddress((void**)&pw1b, g_w1b);
    cudaGetSymbolAddress((void**)&pw2b, g_w2b);

    const int SMEM = 86016;
    cudaFuncSetAttribute(hgemm, cudaFuncAttributeMaxDynamicSharedMemorySize, SMEM);

    // weight prep (tiny, deterministic; reruns each call)
    wsplit<<<256, 256>>>(wq, pwqb, 256, 256);
    wsplit<<<256, 256>>>(wm, pwmb, 256, 256);
    wsplit<<<512, 256>>>(w1, pw1b, 512, 256);
    wsplit<<<512, 256>>>(w2, pw2b, 256, 512);

    // K/V projections (batch-invariant)
    kv_proj<<<M_, C_>>>(wk, bk, wv, bv, bcw);

    const int GX = BN_TOT / 128;   // 1152

    // Q = wq @ feat + bq
    hgemm<<<dim3(GX, 2), 256, SMEM>>>(pwqb, feature, bq, nullptr, pQ, 256, 256, 0);
    // attention
    attn_kernel<<<dim3(BN_TOT / 128, NH_), 128>>>(pQ, pX);
    // merged = wm @ X + bm  (overwrites g_Q)
    hgemm<<<dim3(GX, 2), 256, SMEM>>>(pwmb, pX, bm, nullptr, pQ, 256, 256, 0);
    // cosine reweight
    cos_kernel<<<BN_TOT / 256, 256>>>(pQ, feature, pO);
    // H1 = relu(w1 @ out + b1)
    hgemm<<<dim3(GX, 4), 256, SMEM>>>(pw1b, pO, b1, nullptr, pH1, 512, 256, 1);
    // src = out + w2 @ H1 + b2  (into g_X)
    hgemm<<<dim3(GX, 2), 256, SMEM>>>(pw2b, pH1, b2, pO, pX, 256, 512, 0);
    // LayerNorm -> final output
    ln_kernel<<<BN_TOT / 256, 256>>>(pX, gamma, beta, out);
}

// round 13
// speedup vs baseline: 3.3122x; 1.0956x over previous
#include <cuda_runtime.h>
#include <cuda_bf16.h>
#include <math.h>
#include <stdint.h>

// ---------------- problem constants ----------------
#define B_    64
#define C_    256
#define NPIX  2304          // 48*48
#define BN_TOT (B_ * NPIX)  // 147456 pixels
#define NH_   8
#define DH_   32
#define M_    64
#define DFF_  512

// ---------------- scratch (__device__ globals; no allocs allowed) ----------------
__device__ float    g_kp[C_ * M_];
__device__ float    g_vp[C_ * M_];
__device__ uint32_t g_Qpk [(size_t)C_  * BN_TOT];   // packed split-bf16 (hi | lo<<16)
__device__ uint32_t g_Xpk [(size_t)C_  * BN_TOT];
__device__ uint32_t g_Opk [(size_t)C_  * BN_TOT];
__device__ uint32_t g_H1pk[(size_t)DFF_ * BN_TOT];
// pre-split+tiled weights: per (rowtile rt of 256, kchunk kc of 16):
//   12288 bf16 = hi[256 rows x 24 (16 used)] | lo[same]; rows 48B
__device__ __align__(16) __nv_bfloat16 g_wqb[(size_t)1 * 16 * 12288];
__device__ __align__(16) __nv_bfloat16 g_wmb[(size_t)1 * 16 * 12288];
__device__ __align__(16) __nv_bfloat16 g_w1b[(size_t)2 * 16 * 12288];
__device__ __align__(16) __nv_bfloat16 g_w2b[(size_t)1 * 32 * 12288];

// ---------------- helpers ----------------
__device__ __forceinline__ float fast_exp(float x) {
    x = fmaxf(x, -80.0f);
    float y  = x * 1.4426950408889634f;
    float fk = floorf(y);
    float f  = y - fk;
    float p  = 1.5398e-4f;
    p = fmaf(p, f, 1.3333558e-3f);
    p = fmaf(p, f, 9.6181291e-3f);
    p = fmaf(p, f, 5.5504109e-2f);
    p = fmaf(p, f, 2.4022651e-1f);
    p = fmaf(p, f, 6.9314718e-1f);
    p = fmaf(p, f, 1.0f);
    return __int_as_float(((int)fk + 127) << 23) * p;
}
__device__ __forceinline__ uint32_t pack_split(float v) {
    __nv_bfloat16 h = __float2bfloat16(v);
    __nv_bfloat16 l = __float2bfloat16(v - __bfloat162float(h));
    return (uint32_t)__bfloat16_as_ushort(h) | ((uint32_t)__bfloat16_as_ushort(l) << 16);
}
__device__ __forceinline__ float unpack_f(uint32_t p) {
    return __bfloat162float(__ushort_as_bfloat16((unsigned short)(p & 0xffffu))) +
           __bfloat162float(__ushort_as_bfloat16((unsigned short)(p >> 16)));
}
__device__ __forceinline__ void mma_bf16(float* d, const uint32_t* a, const uint32_t* b) {
    asm volatile("mma.sync.aligned.m16n8k16.row.col.f32.bf16.bf16.f32 "
        "{%0,%1,%2,%3}, {%4,%5,%6,%7}, {%8,%9}, {%0,%1,%2,%3};"
        : "+f"(d[0]), "+f"(d[1]), "+f"(d[2]), "+f"(d[3])
        : "r"(a[0]), "r"(a[1]), "r"(a[2]), "r"(a[3]), "r"(b[0]), "r"(b[1]));
}
__device__ __forceinline__ void ldsm4(uint32_t* r, uint32_t addr) {
    asm volatile("ldmatrix.sync.aligned.m8n8.x4.shared.b16 {%0,%1,%2,%3}, [%4];"
        : "=r"(r[0]), "=r"(r[1]), "=r"(r[2]), "=r"(r[3]) : "r"(addr));
}
__device__ __forceinline__ void ldsm2(uint32_t* r, uint32_t addr) {
    asm volatile("ldmatrix.sync.aligned.m8n8.x2.shared.b16 {%0,%1}, [%2];"
        : "=r"(r[0]), "=r"(r[1]) : "r"(addr));
}
__device__ __forceinline__ void cp16(uint32_t dst, const void* src) {
    asm volatile("cp.async.cg.shared.global [%0], [%1], 16;" :: "r"(dst), "l"(src) : "memory");
}
#define CP_COMMIT() asm volatile("cp.async.commit_group;" ::: "memory")
#define CP_WAIT(n)  asm volatile("cp.async.wait_group %0;" :: "n"(n) : "memory")

// ---------------- weight split/tiling prep ----------------
__global__ void wsplit(const float* __restrict__ W, __nv_bfloat16* __restrict__ dst,
                       int R, int K)
{
    int e = blockIdx.x * 256 + threadIdx.x;
    if (e >= R * K) return;
    int r = e / K, k = e - r * K;
    float v = W[e];
    int rt = r >> 8, rr = r & 255, kc = k >> 4, kk = k & 15;
    size_t base = (size_t)(rt * (K >> 4) + kc) * 12288 + rr * 24 + kk;
    __nv_bfloat16 h = __float2bfloat16(v);
    dst[base]        = h;
    dst[base + 6144] = __float2bfloat16(v - __bfloat162float(h));
}

// ---------------- K/V projections (batch-invariant, tiny) ----------------
__global__ void kv_proj(const float* __restrict__ wk, const float* __restrict__ bk,
                        const float* __restrict__ wv, const float* __restrict__ bv,
                        const float* __restrict__ bcw)
{
    __shared__ float bs[C_];
    int m = blockIdx.x, o = threadIdx.x;
    bs[o] = bcw[m * C_ + o];
    __syncthreads();
    float ak = bk[o], av = bv[o];
    const float* wkr = wk + (size_t)o * C_;
    const float* wvr = wv + (size_t)o * C_;
#pragma unroll 8
    for (int c = 0; c < C_; c++) {
        ak = fmaf(wkr[c], bs[c], ak);
        av = fmaf(wvr[c], bs[c], av);
    }
    g_kp[o * M_ + m] = ak;
    g_vp[o * M_ + m] = av;
}

// ---------------- pipelined HMMA split-bf16 GEMM, 256 rows x 64 px tile ----------------
// 8 warps: wm=wid&3 (4 x 64 rows), wn=wid>>2 (2 x 32 px). Kc=16.
// smem 98304B: W ring x3 @0 (24576 ea: hi 12288|lo 12288),
//              stage ring x3 @73728 (4096 ea), X planes x2 @86016 (6144 ea: hi 3072|lo 3072)
// EPI: 0 = bias(+relu) -> packed u32.  1 = bias + fused cosine reweight -> packed O.
//      2 = bias + resid(packed) + LayerNorm -> fp32 final out.
template<int EPI, int AF32>
__global__ __launch_bounds__(256, 2)
void hgemm(const __nv_bfloat16* __restrict__ wblk, const void* __restrict__ Xv,
           const float* __restrict__ bias,
           const float* __restrict__ feat,       // EPI==1
           const uint32_t* __restrict__ respk,   // EPI==2
           const float* __restrict__ gamma, const float* __restrict__ beta,  // EPI==2
           void* __restrict__ Yv, int R, int K, int act)
{
    extern __shared__ char sm[];
    const int tid  = threadIdx.x;
    const int lane = tid & 31, wid = tid >> 5;
    const int wm = wid & 3, wn = wid >> 2;
    const int n0g = blockIdx.x * 64;             // NPIX % 64 == 0 -> never crosses batch
    const int b   = n0g / NPIX;
    const int nn  = n0g - b * NPIX;
    const int rt  = blockIdx.y;
    const int NCH = K >> 4;
    const uint32_t sb = (uint32_t)__cvta_generic_to_shared(sm);
    const char* Xb = (const char*)Xv + ((size_t)b * K * NPIX + nn) * 4;

    float acc[4][4][4];
#pragma unroll
    for (int i = 0; i < 4; i++)
#pragma unroll
        for (int j = 0; j < 4; j++)
#pragma unroll
            for (int q = 0; q < 4; q++) acc[i][j][q] = 0.0f;

    auto load_chunk = [&](int kc) {
        const int s = kc % 3;
        const uint4* ws = (const uint4*)(wblk + (size_t)(rt * NCH + kc) * 12288);
        const uint32_t wdst = sb + s * 24576;
#pragma unroll
        for (int j = 0; j < 6; j++)
            cp16(wdst + (tid + j * 256) * 16, ws + tid + j * 256);
        const uint32_t sdst = sb + 73728 + s * 4096;
        cp16(sdst + tid * 16,
             Xb + ((size_t)(kc * 16 + (tid >> 4)) * NPIX + (tid & 15) * 4) * 4);
        CP_COMMIT();
    };

    auto convert = [&](int kc) {
        const int s = kc % 3;
        const char* stg = sm + 73728 + s * 4096;
        char* pl = sm + 86016 + (kc & 1) * 6144;
        const int px = tid & 63, kseg = tid >> 6;   // 4 k's per thread
        uint32_t hv[2], lv[2];
        if (AF32) {
            const float* st = (const float*)stg;
#pragma unroll
            for (int t = 0; t < 2; t++) {
                float v0 = st[(kseg * 4 + 2 * t    ) * 64 + px];
                float v1 = st[(kseg * 4 + 2 * t + 1) * 64 + px];
                __nv_bfloat16 h0 = __float2bfloat16(v0), h1 = __float2bfloat16(v1);
                __nv_bfloat16 l0 = __float2bfloat16(v0 - __bfloat162float(h0));
                __nv_bfloat16 l1 = __float2bfloat16(v1 - __bfloat162float(h1));
                hv[t] = (uint32_t)__bfloat16_as_ushort(h0) | ((uint32_t)__bfloat16_as_ushort(h1) << 16);
                lv[t] = (uint32_t)__bfloat16_as_ushort(l0) | ((uint32_t)__bfloat16_as_ushort(l1) << 16);
            }
        } else {
            const uint32_t* st = (const uint32_t*)stg;
#pragma unroll
            for (int t = 0; t < 2; t++) {
                uint32_t w0 = st[(kseg * 4 + 2 * t    ) * 64 + px];
                uint32_t w1 = st[(kseg * 4 + 2 * t + 1) * 64 + px];
                hv[t] = (w0 & 0xffffu) | (w1 << 16);
                lv[t] = (w0 >> 16)     | (w1 & 0xffff0000u);
            }
        }
        *(uint2*)(pl +        px * 48 + kseg * 8) = make_uint2(hv[0], hv[1]);
        *(uint2*)(pl + 3072 + px * 48 + kseg * 8) = make_uint2(lv[0], lv[1]);
    };

    auto do_mma = [&](int kc) {
        const uint32_t sbW = sb + (kc % 3) * 24576;
        const uint32_t sbX = sb + 86016 + (kc & 1) * 6144;
        uint32_t bh[4][2], bl[4][2];
#pragma unroll
        for (int nt = 0; nt < 4; nt++) {
            int rowB = wn * 32 + nt * 8 + (lane & 7);
            uint32_t ab = sbX + rowB * 48 + ((lane >> 3) & 1) * 16;
            ldsm2(bh[nt], ab);
            ldsm2(bl[nt], ab + 3072);
        }
#pragma unroll
        for (int mt = 0; mt < 4; mt++) {
            int rowA = wm * 64 + mt * 16 + (lane & 7) + ((lane >> 3) & 1) * 8;
            uint32_t aa = sbW + rowA * 48 + (lane >> 4) * 16;
            uint32_t ah[4], al[4];
            ldsm4(ah, aa);
            ldsm4(al, aa + 12288);
#pragma unroll
            for (int nt = 0; nt < 4; nt++) {
                mma_bf16(acc[mt][nt], ah, bh[nt]);
                mma_bf16(acc[mt][nt], ah, bl[nt]);
                mma_bf16(acc[mt][nt], al, bh[nt]);
            }
        }
    };

    load_chunk(0);
    load_chunk(1);
    CP_WAIT(1);
    __syncthreads();
    convert(0);
    for (int kc = 0; kc < NCH; kc++) {
        __syncthreads();
        if (kc + 2 < NCH) load_chunk(kc + 2);
        do_mma(kc);
        if (kc + 1 < NCH) convert(kc + 1);
        CP_WAIT(0);
    }

    const int g = lane >> 2, q = lane & 3;

    if (EPI == 0) {
        uint32_t* Y = (uint32_t*)Yv;
#pragma unroll
        for (int mt = 0; mt < 4; mt++) {
            int r0 = rt * 256 + wm * 64 + mt * 16 + g;
            float b0v = __ldg(bias + r0), b1v = __ldg(bias + r0 + 8);
#pragma unroll
            for (int nt = 0; nt < 4; nt++) {
                int px0 = nn + wn * 32 + nt * 8 + 2 * q;
                size_t off0 = ((size_t)b * R + r0) * NPIX + px0;
                size_t off1 = off0 + (size_t)8 * NPIX;
                float v0 = acc[mt][nt][0] + b0v, v1 = acc[mt][nt][1] + b0v;
                float v2 = acc[mt][nt][2] + b1v, v3 = acc[mt][nt][3] + b1v;
                if (act) {
                    v0 = fmaxf(v0, 0.f); v1 = fmaxf(v1, 0.f);
                    v2 = fmaxf(v2, 0.f); v3 = fmaxf(v3, 0.f);
                }
                *(uint2*)(Y + off0) = make_uint2(pack_split(v0), pack_split(v1));
                *(uint2*)(Y + off1) = make_uint2(pack_split(v2), pack_split(v3));
            }
        }
        return;
    }

    // ---- fused epilogues (R == 256, rt == 0): smem reuse after mainloop
    __syncthreads();
    float* sV = (float*)sm;                      // [256][64]
    float* p0 = (float*)(sm + 65536);            // [4][64]
    float* p1 = (float*)(sm + 66560);            // [4][64]
    float* p2 = (float*)(sm + 67584);            // [4][64] (cos only)
    float* sc0 = (float*)(sm + 68608);           // [64]
    float* sc1 = (float*)(sm + 68864);           // [64]

    // frag phase: sV[c][px] = acc + bias
#pragma unroll
    for (int mt = 0; mt < 4; mt++) {
        int c0 = wm * 64 + mt * 16 + g;
        float b0v = __ldg(bias + c0), b1v = __ldg(bias + c0 + 8);
#pragma unroll
        for (int nt = 0; nt < 4; nt++) {
            int px0 = wn * 32 + nt * 8 + 2 * q;
            sV[c0 * 64 + px0]           = acc[mt][nt][0] + b0v;
            sV[c0 * 64 + px0 + 1]       = acc[mt][nt][1] + b0v;
            sV[(c0 + 8) * 64 + px0]     = acc[mt][nt][2] + b1v;
            sV[(c0 + 8) * 64 + px0 + 1] = acc[mt][nt][3] + b1v;
        }
    }
    __syncthreads();

    const int px = tid & 63, cseg = tid >> 6;

    if (EPI == 1) {
        // cos: dot(merged,feat), |merged|^2, |feat|^2 ; overwrite sV with feat
        const float* F = feat + ((size_t)b * 256 + cseg * 64) * NPIX + nn;
        float dsum = 0.f, msum = 0.f, fsum = 0.f;
#pragma unroll 8
        for (int cc = 0; cc < 64; cc++) {
            float v = sV[(cseg * 64 + cc) * 64 + px];
            float f = F[(size_t)cc * NPIX + px];
            dsum = fmaf(v, f, dsum);
            msum = fmaf(v, v, msum);
            fsum = fmaf(f, f, fsum);
            sV[(cseg * 64 + cc) * 64 + px] = f;
        }
        p0[cseg * 64 + px] = dsum;
        p1[cseg * 64 + px] = msum;
        p2[cseg * 64 + px] = fsum;
        __syncthreads();
        if (tid < 64) {
            float d = p0[tid] + p0[64 + tid] + p0[128 + tid] + p0[192 + tid];
            float m2 = p1[tid] + p1[64 + tid] + p1[128 + tid] + p1[192 + tid];
            float f2 = p2[tid] + p2[64 + tid] + p2[128 + tid] + p2[192 + tid];
            sc0[tid] = d / ((sqrtf(m2) + 1e-5f) * (sqrtf(f2) + 1e-5f)) + 1.0f;
        }
        __syncthreads();
        uint32_t* Y = (uint32_t*)Yv + (size_t)b * 256 * NPIX + nn;
#pragma unroll
        for (int i = 0; i < 16; i++) {
            int idx = tid + i * 256;
            int c = idx >> 4, p4 = (idx & 15) * 4;
            float4 f4 = *(float4*)&sV[c * 64 + p4];
            uint4 o;
            o.x = pack_split(f4.x * sc0[p4]);
            o.y = pack_split(f4.y * sc0[p4 + 1]);
            o.z = pack_split(f4.z * sc0[p4 + 2]);
            o.w = pack_split(f4.w * sc0[p4 + 3]);
            *(uint4*)&Y[(size_t)c * NPIX + p4] = o;
        }
    } else {
        // EPI == 2: residual + LayerNorm -> fp32 final output
        const uint32_t* Rp = respk + ((size_t)b * 256 + cseg * 64) * NPIX + nn;
        float s = 0.f, s2 = 0.f;
#pragma unroll 8
        for (int cc = 0; cc < 64; cc++) {
            float v = sV[(cseg * 64 + cc) * 64 + px] + unpack_f(Rp[(size_t)cc * NPIX + px]);
            sV[(cseg * 64 + cc) * 64 + px] = v;
            s += v;
            s2 = fmaf(v, v, s2);
        }
        p0[cseg * 64 + px] = s;
        p1[cseg * 64 + px] = s2;
        __syncthreads();
        if (tid < 64) {
            float ss = p0[tid] + p0[64 + tid] + p0[128 + tid] + p0[192 + tid];
            float ss2 = p1[tid] + p1[64 + tid] + p1[128 + tid] + p1[192 + tid];
            float mu = ss * (1.0f / 256.0f);
            float var = ss2 * (1.0f / 256.0f) - mu * mu;
            sc0[tid] = mu;
            sc1[tid] = rsqrtf(var + 1e-5f);
        }
        __syncthreads();
        float* Y = (float*)Yv + (size_t)b * 256 * NPIX + nn;
#pragma unroll
        for (int i = 0; i < 16; i++) {
            int idx = tid + i * 256;
            int c = idx >> 4, p4 = (idx & 15) * 4;
            float gm = __ldg(gamma + c), bt = __ldg(beta + c);
            float4 v4 = *(float4*)&sV[c * 64 + p4];
            float4 o;
            o.x = (v4.x - sc0[p4])     * sc1[p4]     * gm + bt;
            o.y = (v4.y - sc0[p4 + 1]) * sc1[p4 + 1] * gm + bt;
            o.z = (v4.z - sc0[p4 + 2]) * sc1[p4 + 2] * gm + bt;
            o.w = (v4.w - sc0[p4 + 3]) * sc1[p4 + 3] * gm + bt;
            *(float4*)&Y[(size_t)c * NPIX + p4] = o;
        }
    }
}

// ---------------- attention: packed I/O, otherwise validated structure ----------------
__global__ __launch_bounds__(128)
void attn_kernel(const uint32_t* __restrict__ Qpk, uint32_t* __restrict__ Xpk)
{
    __shared__ float kps[DH_][M_];
    __shared__ float vps[DH_][M_];
    const int h   = blockIdx.y;
    const int tid = threadIdx.x;
    for (int i = tid; i < DH_ * M_; i += 128) {
        int d = i >> 6, m = i & 63;
        kps[d][m] = g_kp[(d * NH_ + h) * M_ + m];
        vps[d][m] = g_vp[(d * NH_ + h) * M_ + m];
    }
    __syncthreads();

    const int j = blockIdx.x * 128 + tid;
    const int b = j / NPIX;
    const int n = j - b * NPIX;
    const uint32_t* Qb = Qpk + (size_t)b * C_ * NPIX + n;

    float s[M_];
#pragma unroll
    for (int m = 0; m < M_; m++) s[m] = 0.0f;
#pragma unroll
    for (int d = 0; d < DH_; d++) {
        float qd = unpack_f(Qb[(size_t)(d * NH_ + h) * NPIX]);
#pragma unroll
        for (int m = 0; m < M_; m++) s[m] = fmaf(qd, kps[d][m], s[m]);
    }
    float mx = s[0];
#pragma unroll
    for (int m = 1; m < M_; m++) mx = fmaxf(mx, s[m]);
    float ssum = 0.0f;
#pragma unroll
    for (int m = 0; m < M_; m++) {
        float e = fast_exp((s[m] - mx) * 0.17677669529663687f);
        s[m] = e;
        ssum += e;
    }
    float inv = 1.0f / ssum;
    uint32_t* Xb = Xpk + (size_t)b * C_ * NPIX + n;
#pragma unroll
    for (int d = 0; d < DH_; d++) {
        float acc = 0.0f;
#pragma unroll
        for (int m = 0; m < M_; m++) acc = fmaf(s[m], vps[d][m], acc);
        Xb[(size_t)(d * NH_ + h) * NPIX] = pack_split(acc * inv);
    }
}

// ---------------- host orchestration ----------------
extern "C" void kernel_launch(void* const* d_in, const int* in_sizes, int n_in,
                              void* d_out, int out_size)
{
    const float* feature = (const float*)d_in[0];
    const float* bcw     = (const float*)d_in[1];
    const float* wq      = (const float*)d_in[2];
    const float* bq      = (const float*)d_in[3];
    const float* wk      = (const float*)d_in[4];
    const float* bk      = (const float*)d_in[5];
    const float* wv      = (const float*)d_in[6];
    const float* bv      = (const float*)d_in[7];
    const float* wm      = (const float*)d_in[8];
    const float* bm      = (const float*)d_in[9];
    const float* w1      = (const float*)d_in[10];
    const float* b1      = (const float*)d_in[11];
    const float* w2      = (const float*)d_in[12];
    const float* b2      = (const float*)d_in[13];
    const float* gamma   = (const float*)d_in[14];
    const float* beta    = (const float*)d_in[15];
    float* out = (float*)d_out;

    uint32_t *pQ, *pX, *pO, *pH1;
    __nv_bfloat16 *pwqb, *pwmb, *pw1b, *pw2b;
    cudaGetSymbolAddress((void**)&pQ,   g_Qpk);
    cudaGetSymbolAddress((void**)&pX,   g_Xpk);
    cudaGetSymbolAddress((void**)&pO,   g_Opk);
    cudaGetSymbolAddress((void**)&pH1,  g_H1pk);
    cudaGetSymbolAddress((void**)&pwqb, g_wqb);
    cudaGetSymbolAddress((void**)&pwmb, g_wmb);
    cudaGetSymbolAddress((void**)&pw1b, g_w1b);
    cudaGetSymbolAddress((void**)&pw2b, g_w2b);

    const int SMEM = 98304;
    cudaFuncSetAttribute(hgemm<0,1>, cudaFuncAttributeMaxDynamicSharedMemorySize, SMEM);
    cudaFuncSetAttribute(hgemm<0,0>, cudaFuncAttributeMaxDynamicSharedMemorySize, SMEM);
    cudaFuncSetAttribute(hgemm<1,0>, cudaFuncAttributeMaxDynamicSharedMemorySize, SMEM);
    cudaFuncSetAttribute(hgemm<2,0>, cudaFuncAttributeMaxDynamicSharedMemorySize, SMEM);

    // weight prep (tiny, deterministic; reruns each call)
    wsplit<<<256, 256>>>(wq, pwqb, 256, 256);
    wsplit<<<256, 256>>>(wm, pwmb, 256, 256);
    wsplit<<<512, 256>>>(w1, pw1b, 512, 256);
    wsplit<<<512, 256>>>(w2, pw2b, 256, 512);

    // K/V projections (batch-invariant)
    kv_proj<<<M_, C_>>>(wk, bk, wv, bv, bcw);

    const int GX = BN_TOT / 64;   // 2304

    // Q = wq @ feat + bq  -> packed
    hgemm<0,1><<<dim3(GX, 1), 256, SMEM>>>(pwqb, feature, bq,
        nullptr, nullptr, nullptr, nullptr, pQ, 256, 256, 0);
    // attention (packed in/out)
    attn_kernel<<<dim3(BN_TOT / 128, NH_), 128>>>(pQ, pX);
    // merged = wm @ X + bm, fused cosine reweight -> packed O
    hgemm<1,0><<<dim3(GX, 1), 256, SMEM>>>(pwmb, pX, bm,
        feature, nullptr, nullptr, nullptr, pO, 256, 256, 0);
    // H1 = relu(w1 @ O + b1) -> packed
    hgemm<0,0><<<dim3(GX, 2), 256, SMEM>>>(pw1b, pO, b1,
        nullptr, nullptr, nullptr, nullptr, pH1, 512, 256, 1);
    // out = LN(O + w2 @ H1 + b2) -> fp32 final output
    hgemm<2,0><<<dim3(GX, 1), 256, SMEM>>>(pw2b, pH1, b2,
        nullptr, pO, gamma, beta, out, 256, 512, 0);
}